// round 3
// baseline (speedup 1.0000x reference)
#include <cuda_runtime.h>
#include <cstdint>

// RNN_50036368998466: B=1048576, T=3, H=32, D_IN=1.
// 2 batch elements per lane via fma.rn.f32x2; duplicated (w,w) weights in shared,
// fetched 2-at-a-time with LDS.128. Dataflow: h1 direct -> scatter into acc (step2
// pre-act) -> tanh in place (h2) -> gather for step3. Peak arrays: acc[32]+o1[16]
// = 48 u64 = 96 regs (no spill).

typedef unsigned long long u64;

__device__ __forceinline__ u64 pk2(float lo, float hi) {
    u64 r; asm("mov.b64 %0, {%1,%2};" : "=l"(r) : "f"(lo), "f"(hi)); return r;
}
__device__ __forceinline__ float2 up2(u64 v) {
    float2 r; asm("mov.b64 {%0,%1}, %2;" : "=f"(r.x), "=f"(r.y) : "l"(v)); return r;
}
__device__ __forceinline__ u64 f2u(float2 v) { return pk2(v.x, v.y); }
__device__ __forceinline__ u64 fma2(u64 a, u64 b, u64 c) {
    u64 d; asm("fma.rn.f32x2 %0, %1, %2, %3;" : "=l"(d) : "l"(a), "l"(b), "l"(c)); return d;
}
// load two adjacent duplicated weights (float2 pairs) with one LDS.128
__device__ __forceinline__ void ld2w(const float2* p, u64& w0, u64& w1) {
    float4 v = *reinterpret_cast<const float4*>(p);
    w0 = pk2(v.x, v.y);
    w1 = pk2(v.z, v.w);
}

// tanh(x) = 1 - 2/(exp(2x)+1) via ex2.approx + rcp.approx (abs err ~1e-7).
__device__ __forceinline__ float tanh_fast(float x) {
    float ex;
    asm("ex2.approx.f32 %0, %1;" : "=f"(ex) : "f"(x * 2.8853900817779268f)); // 2*log2(e)
    float r;
    asm("rcp.approx.f32 %0, %1;" : "=f"(r) : "f"(ex + 1.0f));
    return fmaf(-2.0f, r, 1.0f);
}
__device__ __forceinline__ void tanh2(u64 a, u64& t, u64& r) {
    float2 v = up2(a);
    float t0 = tanh_fast(v.x);
    float t1 = tanh_fast(v.y);
    t = pk2(t0, t1);
    r = pk2(fmaxf(t0, 0.0f), fmaxf(t1, 0.0f));
}
__device__ __forceinline__ u64 relu2(u64 a) {
    float2 v = up2(a);
    return pk2(fmaxf(v.x, 0.0f), fmaxf(v.y, 0.0f));
}

__global__ __launch_bounds__(128, 1)
void rnn_fused_kernel(const float* __restrict__ x,
                      const float* __restrict__ W_ih,
                      const float* __restrict__ W_hh,
                      const float* __restrict__ b_ih,
                      const float* __restrict__ b_hh,
                      const float* __restrict__ W1,
                      const float* __restrict__ b1,
                      const float* __restrict__ W2,
                      const float* __restrict__ b2,
                      const float* __restrict__ W3,
                      const float* __restrict__ b3,
                      float* __restrict__ out,
                      int n_pairs) {
    // duplicated (w,w) float2 weights, 16B-aligned for LDS.128 pair fetch
    __shared__ __align__(16) float2 sWih[32];      // W_ih[:,0]
    __shared__ __align__(16) float2 sB[32];        // b_ih + b_hh
    __shared__ __align__(16) float2 sWhhT[1024];   // [j*32+k] = W_hh[k][j]  (scatter, step2)
    __shared__ __align__(16) float2 sWhhR[1024];   // [j*32+k] = W_hh[j][k]  (gather, step3)
    __shared__ __align__(16) float2 sW1T[1536];    // [col*16+i] = W1[i][col]
    __shared__ __align__(16) float2 sB1[16];
    __shared__ __align__(16) float2 sW2[128];      // [i*16+k]
    __shared__ __align__(16) float2 sB2[8];
    __shared__ __align__(16) float2 sW3[8];
    __shared__ float sB3;

    const int tid = threadIdx.x;
    for (int idx = tid; idx < 1024; idx += blockDim.x) {
        int j = idx >> 5, k = idx & 31;
        float wt = W_hh[k * 32 + j]; sWhhT[idx] = make_float2(wt, wt);
        float wr = W_hh[idx];        sWhhR[idx] = make_float2(wr, wr);
    }
    for (int idx = tid; idx < 1536; idx += blockDim.x) {
        int col = idx >> 4, i = idx & 15;
        float w = W1[i * 96 + col];  sW1T[idx] = make_float2(w, w);
    }
    for (int idx = tid; idx < 128; idx += blockDim.x) {
        float w = W2[idx]; sW2[idx] = make_float2(w, w);
    }
    if (tid < 32) {
        float w = W_ih[tid]; sWih[tid] = make_float2(w, w);
        float bb = b_ih[tid] + b_hh[tid]; sB[tid] = make_float2(bb, bb);
    }
    if (tid < 16) { float w = b1[tid]; sB1[tid] = make_float2(w, w); }
    if (tid < 8)  { float w = b2[tid]; sB2[tid] = make_float2(w, w);
                    float v = W3[tid]; sW3[tid] = make_float2(v, v); }
    if (tid == 0) sB3 = b3[0];
    __syncthreads();

    const int gid = blockIdx.x * blockDim.x + tid;
    if (gid >= n_pairs) return;

    // two consecutive batch elements; x flat: [e0t0,e0t1,e0t2, e1t0,e1t1,e1t2]
    const float2* xp = reinterpret_cast<const float2*>(x) + (size_t)gid * 3;
    float2 xa = xp[0], xb = xp[1], xc = xp[2];
    u64 X1 = pk2(xa.x, xb.y);
    u64 X2 = pk2(xa.y, xc.x);
    u64 X3 = pk2(xb.x, xc.y);

    u64 o1[16];
#pragma unroll
    for (int i = 0; i < 16; i++) o1[i] = f2u(sB1[i]);

    // acc = step-2 pre-activation accumulator (becomes h2 in place)
    u64 acc[32];
#pragma unroll
    for (int k = 0; k < 32; k++)
        acc[k] = fma2(X2, f2u(sWih[k]), f2u(sB[k]));

    // ---- Phase 1: h1_j = tanh(X1*wih_j + b_j); scatter into acc, accumulate o1 ----
#pragma unroll
    for (int j = 0; j < 32; j++) {
        u64 pre = fma2(X1, f2u(sWih[j]), f2u(sB[j]));
        u64 t, r;
        tanh2(pre, t, r);
#pragma unroll
        for (int k = 0; k < 32; k += 2) {
            u64 w0, w1; ld2w(&sWhhT[j * 32 + k], w0, w1);
            acc[k]     = fma2(t, w0, acc[k]);
            acc[k + 1] = fma2(t, w1, acc[k + 1]);
        }
#pragma unroll
        for (int i = 0; i < 16; i += 2) {
            u64 w0, w1; ld2w(&sW1T[j * 16 + i], w0, w1);   // col = j
            o1[i]     = fma2(r, w0, o1[i]);
            o1[i + 1] = fma2(r, w1, o1[i + 1]);
        }
    }

    // ---- Phase 2: h2_j = tanh(acc[j]) in place; accumulate o1 (cols 32..63) ----
#pragma unroll
    for (int j = 0; j < 32; j++) {
        u64 t, r;
        tanh2(acc[j], t, r);
        acc[j] = t;
#pragma unroll
        for (int i = 0; i < 16; i += 2) {
            u64 w0, w1; ld2w(&sW1T[(32 + j) * 16 + i], w0, w1);
            o1[i]     = fma2(r, w0, o1[i]);
            o1[i + 1] = fma2(r, w1, o1[i + 1]);
        }
    }

    // ---- Phase 3: gather h3_j = tanh(X3*wih_j + b_j + sum_k h2_k*Whh[j][k]) ----
#pragma unroll
    for (int j = 0; j < 32; j++) {
        u64 preA = fma2(X3, f2u(sWih[j]), f2u(sB[j]));
        u64 preB = pk2(0.0f, 0.0f);
#pragma unroll
        for (int k = 0; k < 32; k += 2) {
            u64 w0, w1; ld2w(&sWhhR[j * 32 + k], w0, w1);
            preA = fma2(acc[k],     w0, preA);
            preB = fma2(acc[k + 1], w1, preB);
        }
        float2 a = up2(preA), b = up2(preB);
        u64 pre = pk2(a.x + b.x, a.y + b.y);
        u64 t, r;
        tanh2(pre, t, r);
        (void)t;
#pragma unroll
        for (int i = 0; i < 16; i += 2) {
            u64 w0, w1; ld2w(&sW1T[(64 + j) * 16 + i], w0, w1);
            o1[i]     = fma2(r, w0, o1[i]);
            o1[i + 1] = fma2(r, w1, o1[i + 1]);
        }
    }

    // ---- fc2: relu(o1 @ W2^T + b2) ----
    u64 o2[8];
#pragma unroll
    for (int i = 0; i < 8; i++) {
        u64 a2 = f2u(sB2[i]);
#pragma unroll
        for (int k = 0; k < 16; k += 2) {
            u64 w0, w1; ld2w(&sW2[i * 16 + k], w0, w1);
            a2 = fma2(o1[k],     w0, a2);
            a2 = fma2(o1[k + 1], w1, a2);
        }
        o2[i] = relu2(a2);
    }

    // ---- fc3 ----
    u64 a3 = pk2(sB3, sB3);
#pragma unroll
    for (int i = 0; i < 8; i += 2) {
        u64 w0, w1; ld2w(&sW3[i], w0, w1);
        a3 = fma2(o2[i],     w0, a3);
        a3 = fma2(o2[i + 1], w1, a3);
    }

    reinterpret_cast<float2*>(out)[gid] = up2(a3);
}

extern "C" void kernel_launch(void* const* d_in, const int* in_sizes, int n_in,
                              void* d_out, int out_size) {
    const float* x    = (const float*)d_in[0];
    const float* W_ih = (const float*)d_in[1];
    const float* W_hh = (const float*)d_in[2];
    const float* b_ih = (const float*)d_in[3];
    const float* b_hh = (const float*)d_in[4];
    const float* W1   = (const float*)d_in[5];
    const float* b1   = (const float*)d_in[6];
    const float* W2   = (const float*)d_in[7];
    const float* b2   = (const float*)d_in[8];
    const float* W3   = (const float*)d_in[9];
    const float* b3   = (const float*)d_in[10];
    float* out = (float*)d_out;

    const int B = in_sizes[0] / 3;      // x is [B, 3, 1]
    const int n_pairs = B / 2;          // B = 1048576 (even)
    const int threads = 128;
    const int blocks = (n_pairs + threads - 1) / threads;

    rnn_fused_kernel<<<blocks, threads>>>(x, W_ih, W_hh, b_ih, b_hh,
                                          W1, b1, W2, b2, W3, b3,
                                          out, n_pairs);
}

// round 4
// speedup vs baseline: 1.7452x; 1.7452x over previous
#include <cuda_runtime.h>
#include <cstdint>

// RNN_50036368998466: B=1048576, T=3, H=32, D_IN=1.
// Stage 1 (function of scalar x1 only) is tabulated: tbl[idx][48] holds
//   f_k(x1)=bsum_k + sum_j Whh[k][j] tanh(x1*wih_j+bsum_j)   (k=0..31, step-2 preact seed)
//   g_i(x1)=b1_i  + sum_j W1[i][j]  relu(tanh(...))          (i=0..15, fc1 seed)
// Main kernel: 1 element/thread, f32x2 packing over hidden/output index pairs,
// full-width LDS.128 weight fetches (no duplication), 128-reg cap for 4 CTAs/SM.

typedef unsigned long long u64;

#define TBL_N    8192
#define TBL_LO   (-10.0f)
#define TBL_STEP (20.0f / 8191.0f)
#define TBL_INV  (8191.0f / 20.0f)

__device__ __align__(16) float g_tbl[TBL_N * 48];

__device__ __forceinline__ u64 pk2(float lo, float hi) {
    u64 r; asm("mov.b64 %0, {%1,%2};" : "=l"(r) : "f"(lo), "f"(hi)); return r;
}
__device__ __forceinline__ float2 up2(u64 v) {
    float2 r; asm("mov.b64 {%0,%1}, %2;" : "=f"(r.x), "=f"(r.y) : "l"(v)); return r;
}
__device__ __forceinline__ u64 f2u(float2 v) { return pk2(v.x, v.y); }
__device__ __forceinline__ u64 fma2(u64 a, u64 b, u64 c) {
    u64 d; asm("fma.rn.f32x2 %0, %1, %2, %3;" : "=l"(d) : "l"(a), "l"(b), "l"(c)); return d;
}
__device__ __forceinline__ u64 add2(u64 a, u64 b) {
    u64 d; asm("add.rn.f32x2 %0, %1, %2;" : "=l"(d) : "l"(a), "l"(b)); return d;
}
// one LDS.128 -> two packed float2 operands (4 distinct floats)
__device__ __forceinline__ void ld2w(const float2* p, u64& w0, u64& w1) {
    float4 v = *reinterpret_cast<const float4*>(p);
    w0 = pk2(v.x, v.y);
    w1 = pk2(v.z, v.w);
}

// tanh(x) = 1 - 2/(exp(2x)+1) via ex2.approx + rcp.approx (abs err ~1e-7).
__device__ __forceinline__ float tanh_fast(float x) {
    float ex;
    asm("ex2.approx.f32 %0, %1;" : "=f"(ex) : "f"(x * 2.8853900817779268f)); // 2*log2(e)
    float r;
    asm("rcp.approx.f32 %0, %1;" : "=f"(r) : "f"(ex + 1.0f));
    return fmaf(-2.0f, r, 1.0f);
}
__device__ __forceinline__ u64 relu2(u64 a) {
    float2 v = up2(a);
    return pk2(fmaxf(v.x, 0.0f), fmaxf(v.y, 0.0f));
}

// ---------------- table build (runs each launch; ~5us) ----------------
__global__ __launch_bounds__(128)
void build_table(const float* __restrict__ W_ih, const float* __restrict__ W_hh,
                 const float* __restrict__ b_ih, const float* __restrict__ b_hh,
                 const float* __restrict__ W1,   const float* __restrict__ b1) {
    __shared__ float sWih[32], sBsum[32], sWhh[1024], sW1a[512], sB1[16];
    const int tid = threadIdx.x;
    for (int i = tid; i < 1024; i += 128) sWhh[i] = W_hh[i];
    for (int i = tid; i < 512;  i += 128) { int r = i >> 5, c = i & 31; sW1a[i] = W1[r * 96 + c]; }
    if (tid < 32) { sWih[tid] = W_ih[tid]; sBsum[tid] = b_ih[tid] + b_hh[tid]; }
    if (tid < 16) sB1[tid] = b1[tid];
    __syncthreads();

    const int idx = blockIdx.x * 128 + tid;
    if (idx >= TBL_N) return;
    const float x1 = TBL_LO + idx * TBL_STEP;

    float t[32], r[32];
#pragma unroll
    for (int j = 0; j < 32; j++) {
        t[j] = tanh_fast(fmaf(x1, sWih[j], sBsum[j]));
        r[j] = fmaxf(t[j], 0.0f);
    }
    for (int k = 0; k < 32; k++) {
        float f = sBsum[k];
#pragma unroll
        for (int j = 0; j < 32; j++) f = fmaf(sWhh[k * 32 + j], t[j], f);
        g_tbl[idx * 48 + k] = f;
    }
    for (int i = 0; i < 16; i++) {
        float g = sB1[i];
#pragma unroll
        for (int j = 0; j < 32; j++) g = fmaf(sW1a[i * 32 + j], r[j], g);
        g_tbl[idx * 48 + 32 + i] = g;
    }
}

// ---------------- main kernel ----------------
__global__ __launch_bounds__(128, 4)
void rnn_main(const float* __restrict__ x,
              const float* __restrict__ W_ih, const float* __restrict__ W_hh,
              const float* __restrict__ b_ih, const float* __restrict__ b_hh,
              const float* __restrict__ W1,
              const float* __restrict__ W2, const float* __restrict__ b2,
              const float* __restrict__ W3, const float* __restrict__ b3,
              float* __restrict__ out, int B) {
    __shared__ __align__(16) float4 sWihB[16];   // (wih_2m, wih_2m+1, bsum_2m, bsum_2m+1)
    __shared__ __align__(16) float  sWhh[1024];  // row-major W_hh
    __shared__ __align__(16) float2 sW1c[512];   // [(col-32)*8+q] = (W1[2q][col], W1[2q+1][col]), col=32..95
    __shared__ __align__(16) float2 sW2c[64];    // [k*4+m] = (W2[2m][k], W2[2m+1][k])
    __shared__ __align__(16) float2 sB2p[4];
    __shared__ __align__(16) float2 sW3p[4];
    __shared__ float sB3;

    const int tid = threadIdx.x;
    for (int i = tid; i < 1024; i += 128) sWhh[i] = W_hh[i];
    for (int i = tid; i < 512; i += 128) {
        int col = 32 + (i >> 3), q = i & 7;
        sW1c[i] = make_float2(W1[(2 * q) * 96 + col], W1[(2 * q + 1) * 96 + col]);
    }
    if (tid < 64) {
        int k = tid >> 2, m = tid & 3;
        sW2c[tid] = make_float2(W2[(2 * m) * 16 + k], W2[(2 * m + 1) * 16 + k]);
    }
    if (tid < 16)
        sWihB[tid] = make_float4(W_ih[2 * tid], W_ih[2 * tid + 1],
                                 b_ih[2 * tid] + b_hh[2 * tid],
                                 b_ih[2 * tid + 1] + b_hh[2 * tid + 1]);
    if (tid < 4) {
        sB2p[tid] = make_float2(b2[2 * tid], b2[2 * tid + 1]);
        sW3p[tid] = make_float2(W3[2 * tid], W3[2 * tid + 1]);
    }
    if (tid == 0) sB3 = b3[0];
    __syncthreads();

    const int e = blockIdx.x * 128 + tid;
    if (e >= B) return;
    const float xt1 = x[3 * e], xt2 = x[3 * e + 1], xt3 = x[3 * e + 2];

    // ---- stage-1 table lerp: seeds acc (step2 preact pairs) and o1 (fc1 pairs) ----
    float uf = (xt1 - TBL_LO) * TBL_INV;
    uf = fminf(fmaxf(uf, 0.0f), 8190.999f);
    const int i0 = (int)uf;
    const float fr = uf - (float)i0;
    const u64 FR = pk2(fr, fr), NFR = pk2(-fr, -fr);
    const float4* rl = reinterpret_cast<const float4*>(g_tbl + i0 * 48);
    const float4* rh = reinterpret_cast<const float4*>(g_tbl + (i0 + 1) * 48);

    u64 acc[16];  // pairs (k, k+1): step-2 preact, later h2
    u64 o1[8];    // pairs (i, i+1): fc1 accumulators
#pragma unroll
    for (int c = 0; c < 12; c++) {
        float4 lo = rl[c], hi = rh[c];
        u64 L0 = pk2(lo.x, lo.y), L1 = pk2(lo.z, lo.w);
        u64 H0 = pk2(hi.x, hi.y), H1 = pk2(hi.z, hi.w);
        u64 r0 = fma2(FR, H0, fma2(NFR, L0, L0));  // lo + fr*(hi-lo)
        u64 r1 = fma2(FR, H1, fma2(NFR, L1, L1));
        if (c < 8) { acc[2 * c] = r0; acc[2 * c + 1] = r1; }
        else       { o1[2 * (c - 8)] = r0; o1[2 * (c - 8) + 1] = r1; }
    }

    // ---- add x2 * wih to step-2 preact ----
    const u64 X2 = pk2(xt2, xt2);
#pragma unroll
    for (int p = 0; p < 16; p++) {
        float4 wb = sWihB[p];
        acc[p] = fma2(X2, pk2(wb.x, wb.y), acc[p]);
    }

    // ---- phase 2: h2 = tanh(acc) in place; o1 += relu(h2) x W1 cols 32..63 ----
#pragma unroll
    for (int p = 0; p < 16; p++) {
        float2 v = up2(acc[p]);
        float t0 = tanh_fast(v.x), t1 = tanh_fast(v.y);
        acc[p] = pk2(t0, t1);
        float r0 = fmaxf(t0, 0.0f), r1 = fmaxf(t1, 0.0f);
        u64 R0 = pk2(r0, r0), R1 = pk2(r1, r1);
        const int c0 = 2 * p, c1 = 2 * p + 1;  // (col-32)
#pragma unroll
        for (int q = 0; q < 8; q += 2) {
            u64 wa0, wa1; ld2w(&sW1c[c0 * 8 + q], wa0, wa1);
            o1[q]     = fma2(R0, wa0, o1[q]);
            o1[q + 1] = fma2(R0, wa1, o1[q + 1]);
            u64 wb0, wb1; ld2w(&sW1c[c1 * 8 + q], wb0, wb1);
            o1[q]     = fma2(R1, wb0, o1[q]);
            o1[q + 1] = fma2(R1, wb1, o1[q + 1]);
        }
    }

    // ---- phase 3: h3_j = tanh(x3*wih_j + bsum_j + Whh[j]·h2); o1 += relu x W1 cols 64..95 ----
#pragma unroll 2
    for (int m = 0; m < 16; m++) {
        const int j0 = 2 * m, j1 = 2 * m + 1;
        u64 A0a = 0ull, A0b = 0ull, A1a = 0ull, A1b = 0ull;
#pragma unroll
        for (int p = 0; p < 16; p += 2) {
            u64 w0, w1; ld2w(reinterpret_cast<const float2*>(&sWhh[j0 * 32 + 2 * p]), w0, w1);
            A0a = fma2(acc[p], w0, A0a);
            A0b = fma2(acc[p + 1], w1, A0b);
            u64 v0, v1; ld2w(reinterpret_cast<const float2*>(&sWhh[j1 * 32 + 2 * p]), v0, v1);
            A1a = fma2(acc[p], v0, A1a);
            A1b = fma2(acc[p + 1], v1, A1b);
        }
        float2 a0 = up2(add2(A0a, A0b));
        float2 a1 = up2(add2(A1a, A1b));
        float4 wb = sWihB[m];
        float pre0 = fmaf(xt3, wb.x, wb.z) + (a0.x + a0.y);
        float pre1 = fmaf(xt3, wb.y, wb.w) + (a1.x + a1.y);
        float t0 = tanh_fast(pre0), t1 = tanh_fast(pre1);
        float r0 = fmaxf(t0, 0.0f), r1 = fmaxf(t1, 0.0f);
        u64 R0 = pk2(r0, r0), R1 = pk2(r1, r1);
        const int c0 = 32 + j0, c1 = 32 + j1;  // (col-32) for cols 64..95
#pragma unroll
        for (int q = 0; q < 8; q += 2) {
            u64 wa0, wa1; ld2w(&sW1c[c0 * 8 + q], wa0, wa1);
            o1[q]     = fma2(R0, wa0, o1[q]);
            o1[q + 1] = fma2(R0, wa1, o1[q + 1]);
            u64 wb0, wb1; ld2w(&sW1c[c1 * 8 + q], wb0, wb1);
            o1[q]     = fma2(R1, wb0, o1[q]);
            o1[q + 1] = fma2(R1, wb1, o1[q + 1]);
        }
    }

    // ---- fc2 (scatter over k, o2 packed over i-pairs) ----
    u64 o2[4];
#pragma unroll
    for (int m = 0; m < 4; m++) o2[m] = f2u(sB2p[m]);
#pragma unroll
    for (int q = 0; q < 8; q++) {
        float2 v = up2(o1[q]);             // o1_{2q}, o1_{2q+1}
        u64 Ka = pk2(v.x, v.x), Kb = pk2(v.y, v.y);
        const int k0 = 2 * q, k1 = 2 * q + 1;
        u64 w0, w1;
        ld2w(&sW2c[k0 * 4 + 0], w0, w1);
        o2[0] = fma2(Ka, w0, o2[0]); o2[1] = fma2(Ka, w1, o2[1]);
        ld2w(&sW2c[k0 * 4 + 2], w0, w1);
        o2[2] = fma2(Ka, w0, o2[2]); o2[3] = fma2(Ka, w1, o2[3]);
        ld2w(&sW2c[k1 * 4 + 0], w0, w1);
        o2[0] = fma2(Kb, w0, o2[0]); o2[1] = fma2(Kb, w1, o2[1]);
        ld2w(&sW2c[k1 * 4 + 2], w0, w1);
        o2[2] = fma2(Kb, w0, o2[2]); o2[3] = fma2(Kb, w1, o2[3]);
    }

    // ---- relu + fc3 ----
    u64 A = 0ull;
#pragma unroll
    for (int m = 0; m < 4; m++) A = fma2(relu2(o2[m]), f2u(sW3p[m]), A);
    float2 af = up2(A);
    out[e] = af.x + af.y + sB3;
}

extern "C" void kernel_launch(void* const* d_in, const int* in_sizes, int n_in,
                              void* d_out, int out_size) {
    const float* x    = (const float*)d_in[0];
    const float* W_ih = (const float*)d_in[1];
    const float* W_hh = (const float*)d_in[2];
    const float* b_ih = (const float*)d_in[3];
    const float* b_hh = (const float*)d_in[4];
    const float* W1   = (const float*)d_in[5];
    const float* b1   = (const float*)d_in[6];
    const float* W2   = (const float*)d_in[7];
    const float* b2   = (const float*)d_in[8];
    const float* W3   = (const float*)d_in[9];
    const float* b3   = (const float*)d_in[10];
    float* out = (float*)d_out;

    const int B = in_sizes[0] / 3;   // x is [B, 3, 1]

    build_table<<<TBL_N / 128, 128>>>(W_ih, W_hh, b_ih, b_hh, W1, b1);
    rnn_main<<<(B + 127) / 128, 128>>>(x, W_ih, W_hh, b_ih, b_hh,
                                       W1, W2, b2, W3, b3, out, B);
}

// round 5
// speedup vs baseline: 2.2784x; 1.3055x over previous
#include <cuda_runtime.h>
#include <cstdint>

// RNN_50036368998466: B=1048576, T=3, H=32, D_IN=1.
// Stage 1 tabulated (function of x1 only). Main kernel: 2 elements per thread,
// each hidden-index f32x2-packed; every shared-memory weight load (LDS.128)
// feeds BOTH elements, halving smem return-bandwidth per MAC (the R4 bottleneck:
// L1 at 93%, broadcast LDS pays full 512B/instr writeback).

typedef unsigned long long u64;

#define TBL_N    8192
#define TBL_LO   (-10.0f)
#define TBL_STEP (20.0f / 8191.0f)
#define TBL_INV  (8191.0f / 20.0f)

__device__ __align__(16) float g_tbl[TBL_N * 48];

__device__ __forceinline__ u64 pk2(float lo, float hi) {
    u64 r; asm("mov.b64 %0, {%1,%2};" : "=l"(r) : "f"(lo), "f"(hi)); return r;
}
__device__ __forceinline__ float2 up2(u64 v) {
    float2 r; asm("mov.b64 {%0,%1}, %2;" : "=f"(r.x), "=f"(r.y) : "l"(v)); return r;
}
__device__ __forceinline__ u64 f2u(float2 v) { return pk2(v.x, v.y); }
__device__ __forceinline__ u64 fma2(u64 a, u64 b, u64 c) {
    u64 d; asm("fma.rn.f32x2 %0, %1, %2, %3;" : "=l"(d) : "l"(a), "l"(b), "l"(c)); return d;
}
// one LDS.128 -> two packed float2 weight operands (4 distinct floats)
__device__ __forceinline__ void ld2w(const float2* p, u64& w0, u64& w1) {
    float4 v = *reinterpret_cast<const float4*>(p);
    w0 = pk2(v.x, v.y);
    w1 = pk2(v.z, v.w);
}

// tanh(x) = 1 - 2/(exp(2x)+1) via ex2.approx + rcp.approx (abs err ~1e-7).
__device__ __forceinline__ float tanh_fast(float x) {
    float ex;
    asm("ex2.approx.f32 %0, %1;" : "=f"(ex) : "f"(x * 2.8853900817779268f)); // 2*log2(e)
    float r;
    asm("rcp.approx.f32 %0, %1;" : "=f"(r) : "f"(ex + 1.0f));
    return fmaf(-2.0f, r, 1.0f);
}
__device__ __forceinline__ u64 relu2(u64 a) {
    float2 v = up2(a);
    return pk2(fmaxf(v.x, 0.0f), fmaxf(v.y, 0.0f));
}

// ---------------- table build (runs each launch; ~5us) ----------------
__global__ __launch_bounds__(128)
void build_table(const float* __restrict__ W_ih, const float* __restrict__ W_hh,
                 const float* __restrict__ b_ih, const float* __restrict__ b_hh,
                 const float* __restrict__ W1,   const float* __restrict__ b1) {
    __shared__ float sWih[32], sBsum[32], sWhh[1024], sW1a[512], sB1[16];
    const int tid = threadIdx.x;
    for (int i = tid; i < 1024; i += 128) sWhh[i] = W_hh[i];
    for (int i = tid; i < 512;  i += 128) { int r = i >> 5, c = i & 31; sW1a[i] = W1[r * 96 + c]; }
    if (tid < 32) { sWih[tid] = W_ih[tid]; sBsum[tid] = b_ih[tid] + b_hh[tid]; }
    if (tid < 16) sB1[tid] = b1[tid];
    __syncthreads();

    const int idx = blockIdx.x * 128 + tid;
    if (idx >= TBL_N) return;
    const float x1 = TBL_LO + idx * TBL_STEP;

    float t[32], r[32];
#pragma unroll
    for (int j = 0; j < 32; j++) {
        t[j] = tanh_fast(fmaf(x1, sWih[j], sBsum[j]));
        r[j] = fmaxf(t[j], 0.0f);
    }
    for (int k = 0; k < 32; k++) {
        float f = sBsum[k];
#pragma unroll
        for (int j = 0; j < 32; j++) f = fmaf(sWhh[k * 32 + j], t[j], f);
        g_tbl[idx * 48 + k] = f;
    }
    for (int i = 0; i < 16; i++) {
        float g = sB1[i];
#pragma unroll
        for (int j = 0; j < 32; j++) g = fmaf(sW1a[i * 32 + j], r[j], g);
        g_tbl[idx * 48 + 32 + i] = g;
    }
}

// ---------------- main kernel: 2 elements / thread ----------------
__global__ __launch_bounds__(128, 3)
void rnn_main(const float* __restrict__ x,
              const float* __restrict__ W_ih, const float* __restrict__ W_hh,
              const float* __restrict__ b_ih, const float* __restrict__ b_hh,
              const float* __restrict__ W1,
              const float* __restrict__ W2, const float* __restrict__ b2,
              const float* __restrict__ W3, const float* __restrict__ b3,
              float* __restrict__ out, int n_half) {
    __shared__ __align__(16) float4 sWihB[16];   // (wih_2m, wih_2m+1, bsum_2m, bsum_2m+1)
    __shared__ __align__(16) float2 sWhh2[512];  // [j*16+p] = (Whh[j][2p], Whh[j][2p+1])
    __shared__ __align__(16) float2 sW1c[512];   // [(col-32)*8+q] = (W1[2q][col], W1[2q+1][col])
    __shared__ __align__(16) float2 sW2c[64];    // [k*4+m] = (W2[2m][k], W2[2m+1][k])
    __shared__ __align__(16) float2 sB2p[4];
    __shared__ __align__(16) float2 sW3p[4];
    __shared__ float sB3;

    const int tid = threadIdx.x;
    for (int i = tid; i < 512; i += 128) {
        int j = i >> 4, p = i & 15;
        sWhh2[i] = make_float2(W_hh[j * 32 + 2 * p], W_hh[j * 32 + 2 * p + 1]);
    }
    for (int i = tid; i < 512; i += 128) {
        int col = 32 + (i >> 3), q = i & 7;
        sW1c[i] = make_float2(W1[(2 * q) * 96 + col], W1[(2 * q + 1) * 96 + col]);
    }
    if (tid < 64) {
        int k = tid >> 2, m = tid & 3;
        sW2c[tid] = make_float2(W2[(2 * m) * 16 + k], W2[(2 * m + 1) * 16 + k]);
    }
    if (tid < 16)
        sWihB[tid] = make_float4(W_ih[2 * tid], W_ih[2 * tid + 1],
                                 b_ih[2 * tid] + b_hh[2 * tid],
                                 b_ih[2 * tid + 1] + b_hh[2 * tid + 1]);
    if (tid < 4) {
        sB2p[tid] = make_float2(b2[2 * tid], b2[2 * tid + 1]);
        sW3p[tid] = make_float2(W3[2 * tid], W3[2 * tid + 1]);
    }
    if (tid == 0) sB3 = b3[0];
    __syncthreads();

    const int gid = blockIdx.x * 128 + tid;
    if (gid >= n_half) return;

    // elements eA = 2*gid, eB = 2*gid+1; x flat: 6 floats per thread, 8B aligned
    const float2* xp = reinterpret_cast<const float2*>(x) + (size_t)gid * 3;
    float2 v0 = xp[0], v1 = xp[1], v2 = xp[2];
    const float x1A = v0.x, x2A = v0.y, x3A = v1.x;
    const float x1B = v1.y, x2B = v2.x, x3B = v2.y;

    // ---- stage-1 table lerp for both elements ----
    float ufA = fminf(fmaxf((x1A - TBL_LO) * TBL_INV, 0.0f), 8190.999f);
    float ufB = fminf(fmaxf((x1B - TBL_LO) * TBL_INV, 0.0f), 8190.999f);
    const int iA = (int)ufA, iB = (int)ufB;
    const float frA = ufA - (float)iA, frB = ufB - (float)iB;
    const u64 FRA = pk2(frA, frA), NFRA = pk2(-frA, -frA);
    const u64 FRB = pk2(frB, frB), NFRB = pk2(-frB, -frB);
    const float4* rlA = reinterpret_cast<const float4*>(g_tbl + iA * 48);
    const float4* rhA = reinterpret_cast<const float4*>(g_tbl + (iA + 1) * 48);
    const float4* rlB = reinterpret_cast<const float4*>(g_tbl + iB * 48);
    const float4* rhB = reinterpret_cast<const float4*>(g_tbl + (iB + 1) * 48);

    u64 accA[16], accB[16];  // pairs (k,k+1): step-2 preact, later h2
    u64 o1A[8],  o1B[8];     // pairs (i,i+1): fc1 accumulators
#pragma unroll
    for (int c = 0; c < 12; c++) {
        float4 loA = rlA[c], hiA = rhA[c];
        u64 rA0 = fma2(FRA, pk2(hiA.x, hiA.y), fma2(NFRA, pk2(loA.x, loA.y), pk2(loA.x, loA.y)));
        u64 rA1 = fma2(FRA, pk2(hiA.z, hiA.w), fma2(NFRA, pk2(loA.z, loA.w), pk2(loA.z, loA.w)));
        float4 loB = rlB[c], hiB = rhB[c];
        u64 rB0 = fma2(FRB, pk2(hiB.x, hiB.y), fma2(NFRB, pk2(loB.x, loB.y), pk2(loB.x, loB.y)));
        u64 rB1 = fma2(FRB, pk2(hiB.z, hiB.w), fma2(NFRB, pk2(loB.z, loB.w), pk2(loB.z, loB.w)));
        if (c < 8) { accA[2*c] = rA0; accA[2*c+1] = rA1; accB[2*c] = rB0; accB[2*c+1] = rB1; }
        else       { o1A[2*(c-8)] = rA0; o1A[2*(c-8)+1] = rA1; o1B[2*(c-8)] = rB0; o1B[2*(c-8)+1] = rB1; }
    }

    const u64 X2A = pk2(x2A, x2A), X2B = pk2(x2B, x2B);

    // ---- phase 2: h2 = tanh(acc + x2*wih) in place; o1 += relu(h2) x W1 cols 32..63 ----
#pragma unroll
    for (int p = 0; p < 16; p++) {
        float4 wb = sWihB[p];
        u64 W = pk2(wb.x, wb.y);
        float2 vA = up2(fma2(X2A, W, accA[p]));
        float2 vB = up2(fma2(X2B, W, accB[p]));
        float tA0 = tanh_fast(vA.x), tA1 = tanh_fast(vA.y);
        float tB0 = tanh_fast(vB.x), tB1 = tanh_fast(vB.y);
        accA[p] = pk2(tA0, tA1);
        accB[p] = pk2(tB0, tB1);
        u64 RA0 = pk2(fmaxf(tA0,0.f), fmaxf(tA0,0.f)), RA1 = pk2(fmaxf(tA1,0.f), fmaxf(tA1,0.f));
        u64 RB0 = pk2(fmaxf(tB0,0.f), fmaxf(tB0,0.f)), RB1 = pk2(fmaxf(tB1,0.f), fmaxf(tB1,0.f));
        const int c0 = 2 * p, c1 = 2 * p + 1;   // (col-32)
#pragma unroll
        for (int q = 0; q < 8; q += 2) {
            u64 wa0, wa1; ld2w(&sW1c[c0 * 8 + q], wa0, wa1);
            o1A[q]   = fma2(RA0, wa0, o1A[q]);   o1A[q+1] = fma2(RA0, wa1, o1A[q+1]);
            o1B[q]   = fma2(RB0, wa0, o1B[q]);   o1B[q+1] = fma2(RB0, wa1, o1B[q+1]);
            u64 wc0, wc1; ld2w(&sW1c[c1 * 8 + q], wc0, wc1);
            o1A[q]   = fma2(RA1, wc0, o1A[q]);   o1A[q+1] = fma2(RA1, wc1, o1A[q+1]);
            o1B[q]   = fma2(RB1, wc0, o1B[q]);   o1B[q+1] = fma2(RB1, wc1, o1B[q+1]);
        }
    }

    // ---- phase 3: h3_j = tanh(x3*wih_j + bsum_j + Whh[j]·h2); o1 += relu x W1 cols 64..95 ----
#pragma unroll 2
    for (int m = 0; m < 16; m++) {
        const int j0 = 2 * m, j1 = 2 * m + 1;
        u64 dA0 = 0ull, dA1 = 0ull, dB0 = 0ull, dB1 = 0ull;
#pragma unroll
        for (int p = 0; p < 16; p += 2) {
            u64 w0, w1; ld2w(&sWhh2[j0 * 16 + p], w0, w1);
            dA0 = fma2(accA[p], w0, dA0); dA0 = fma2(accA[p+1], w1, dA0);
            dB0 = fma2(accB[p], w0, dB0); dB0 = fma2(accB[p+1], w1, dB0);
            u64 u0, u1; ld2w(&sWhh2[j1 * 16 + p], u0, u1);
            dA1 = fma2(accA[p], u0, dA1); dA1 = fma2(accA[p+1], u1, dA1);
            dB1 = fma2(accB[p], u0, dB1); dB1 = fma2(accB[p+1], u1, dB1);
        }
        float4 wb = sWihB[m];
        float2 sA0 = up2(dA0), sA1 = up2(dA1), sB0 = up2(dB0), sB1v = up2(dB1);
        float tA0 = tanh_fast(fmaf(x3A, wb.x, wb.z) + (sA0.x + sA0.y));
        float tA1 = tanh_fast(fmaf(x3A, wb.y, wb.w) + (sA1.x + sA1.y));
        float tB0 = tanh_fast(fmaf(x3B, wb.x, wb.z) + (sB0.x + sB0.y));
        float tB1 = tanh_fast(fmaf(x3B, wb.y, wb.w) + (sB1v.x + sB1v.y));
        u64 RA0 = pk2(fmaxf(tA0,0.f), fmaxf(tA0,0.f)), RA1 = pk2(fmaxf(tA1,0.f), fmaxf(tA1,0.f));
        u64 RB0 = pk2(fmaxf(tB0,0.f), fmaxf(tB0,0.f)), RB1 = pk2(fmaxf(tB1,0.f), fmaxf(tB1,0.f));
        const int c0 = 32 + j0, c1 = 32 + j1;   // (col-32) for cols 64..95
#pragma unroll
        for (int q = 0; q < 8; q += 2) {
            u64 wa0, wa1; ld2w(&sW1c[c0 * 8 + q], wa0, wa1);
            o1A[q]   = fma2(RA0, wa0, o1A[q]);   o1A[q+1] = fma2(RA0, wa1, o1A[q+1]);
            o1B[q]   = fma2(RB0, wa0, o1B[q]);   o1B[q+1] = fma2(RB0, wa1, o1B[q+1]);
            u64 wc0, wc1; ld2w(&sW1c[c1 * 8 + q], wc0, wc1);
            o1A[q]   = fma2(RA1, wc0, o1A[q]);   o1A[q+1] = fma2(RA1, wc1, o1A[q+1]);
            o1B[q]   = fma2(RB1, wc0, o1B[q]);   o1B[q+1] = fma2(RB1, wc1, o1B[q+1]);
        }
    }

    // ---- fc2: weights shared across A/B ----
    u64 o2A[4], o2B[4];
#pragma unroll
    for (int m = 0; m < 4; m++) { o2A[m] = f2u(sB2p[m]); o2B[m] = f2u(sB2p[m]); }
#pragma unroll
    for (int q = 0; q < 8; q++) {
        float2 vA = up2(o1A[q]), vB = up2(o1B[q]);
        u64 KaA = pk2(vA.x, vA.x), KbA = pk2(vA.y, vA.y);
        u64 KaB = pk2(vB.x, vB.x), KbB = pk2(vB.y, vB.y);
        const int k0 = 2 * q, k1 = 2 * q + 1;
        u64 w0, w1;
        ld2w(&sW2c[k0 * 4 + 0], w0, w1);
        o2A[0] = fma2(KaA, w0, o2A[0]); o2A[1] = fma2(KaA, w1, o2A[1]);
        o2B[0] = fma2(KaB, w0, o2B[0]); o2B[1] = fma2(KaB, w1, o2B[1]);
        ld2w(&sW2c[k0 * 4 + 2], w0, w1);
        o2A[2] = fma2(KaA, w0, o2A[2]); o2A[3] = fma2(KaA, w1, o2A[3]);
        o2B[2] = fma2(KaB, w0, o2B[2]); o2B[3] = fma2(KaB, w1, o2B[3]);
        ld2w(&sW2c[k1 * 4 + 0], w0, w1);
        o2A[0] = fma2(KbA, w0, o2A[0]); o2A[1] = fma2(KbA, w1, o2A[1]);
        o2B[0] = fma2(KbB, w0, o2B[0]); o2B[1] = fma2(KbB, w1, o2B[1]);
        ld2w(&sW2c[k1 * 4 + 2], w0, w1);
        o2A[2] = fma2(KbA, w0, o2A[2]); o2A[3] = fma2(KbA, w1, o2A[3]);
        o2B[2] = fma2(KbB, w0, o2B[2]); o2B[3] = fma2(KbB, w1, o2B[3]);
    }

    // ---- relu + fc3 ----
    u64 AA = 0ull, AB = 0ull;
#pragma unroll
    for (int m = 0; m < 4; m++) {
        u64 w = f2u(sW3p[m]);
        AA = fma2(relu2(o2A[m]), w, AA);
        AB = fma2(relu2(o2B[m]), w, AB);
    }
    float2 fa = up2(AA), fb = up2(AB);
    float2 res = make_float2(fa.x + fa.y + sB3, fb.x + fb.y + sB3);
    reinterpret_cast<float2*>(out)[gid] = res;
}

extern "C" void kernel_launch(void* const* d_in, const int* in_sizes, int n_in,
                              void* d_out, int out_size) {
    const float* x    = (const float*)d_in[0];
    const float* W_ih = (const float*)d_in[1];
    const float* W_hh = (const float*)d_in[2];
    const float* b_ih = (const float*)d_in[3];
    const float* b_hh = (const float*)d_in[4];
    const float* W1   = (const float*)d_in[5];
    const float* b1   = (const float*)d_in[6];
    const float* W2   = (const float*)d_in[7];
    const float* b2   = (const float*)d_in[8];
    const float* W3   = (const float*)d_in[9];
    const float* b3   = (const float*)d_in[10];
    float* out = (float*)d_out;

    const int B = in_sizes[0] / 3;   // x is [B, 3, 1]
    const int n_half = B / 2;        // B = 1048576 (even)

    build_table<<<TBL_N / 128, 128>>>(W_ih, W_hh, b_ih, b_hh, W1, b1);
    rnn_main<<<(n_half + 127) / 128, 128>>>(x, W_ih, W_hh, b_ih, b_hh,
                                            W1, W2, b2, W3, b3, out, n_half);
}

// round 6
// speedup vs baseline: 2.7930x; 1.2259x over previous
#include <cuda_runtime.h>
#include <cstdint>

// RNN_50036368998466: B=1048576, T=3, H=32, D_IN=1.
// Stage 1 tabulated (function of x1 only). Weights moved to __constant__ bank
// (uniform-port LDCU, zero L1 wavefronts) — R5 was bound at L1=81% because
// broadcast LDS.128 still pays full 512B wavefronts for 16B of unique weight.
// Pipeline: prep kernel packs weights -> device scratch -> memcpyToSymbol (D2D)
// -> table build -> main kernel (2 elements/thread, f32x2 hidden-packed).

typedef unsigned long long u64;

#define TBL_N    8192
#define TBL_LO   (-10.0f)
#define TBL_STEP (20.0f / 8191.0f)
#define TBL_INV  (8191.0f / 20.0f)

__device__ __align__(16) float g_tbl[TBL_N * 48];
__device__ __align__(16) float g_wbuf[2304];
__constant__ __align__(16) float cbuf[2304];

// float offsets inside cbuf (all 16B aligned where float4-read)
#define OFF_WIHB 0      // float4[16]: (wih_2m, wih_2m+1, bsum_2m, bsum_2m+1)
#define OFF_WHH2 64     // float2[512]: [j*16+p] = (Whh[j][2p], Whh[j][2p+1])  (== raw row-major)
#define OFF_W1C  1088   // float2[512]: [(col-32)*8+q] = (W1[2q][col], W1[2q+1][col])
#define OFF_W2C  2112   // float2[64]:  [k*4+m] = (W2[2m][k], W2[2m+1][k])
#define OFF_B2P  2240   // float2[4]
#define OFF_W3P  2248   // float2[4]
#define OFF_B3   2256

__device__ __forceinline__ u64 pk2(float lo, float hi) {
    u64 r; asm("mov.b64 %0, {%1,%2};" : "=l"(r) : "f"(lo), "f"(hi)); return r;
}
__device__ __forceinline__ float2 up2(u64 v) {
    float2 r; asm("mov.b64 {%0,%1}, %2;" : "=f"(r.x), "=f"(r.y) : "l"(v)); return r;
}
__device__ __forceinline__ u64 fma2(u64 a, u64 b, u64 c) {
    u64 d; asm("fma.rn.f32x2 %0, %1, %2, %3;" : "=l"(d) : "l"(a), "l"(b), "l"(c)); return d;
}
// two packed weight operands from one 16B constant-bank read (compile-time index)
__device__ __forceinline__ void ld2wc(int fidx, u64& w0, u64& w1) {
    float4 v = *reinterpret_cast<const float4*>(&cbuf[fidx]);
    w0 = pk2(v.x, v.y);
    w1 = pk2(v.z, v.w);
}

// tanh(x) = 1 - 2/(exp(2x)+1) via ex2.approx + rcp.approx (abs err ~1e-7).
__device__ __forceinline__ float tanh_fast(float x) {
    float ex;
    asm("ex2.approx.f32 %0, %1;" : "=f"(ex) : "f"(x * 2.8853900817779268f)); // 2*log2(e)
    float r;
    asm("rcp.approx.f32 %0, %1;" : "=f"(r) : "f"(ex + 1.0f));
    return fmaf(-2.0f, r, 1.0f);
}
__device__ __forceinline__ u64 relu2(u64 a) {
    float2 v = up2(a);
    return pk2(fmaxf(v.x, 0.0f), fmaxf(v.y, 0.0f));
}

// ---------------- weight pack kernel ----------------
__global__ __launch_bounds__(256)
void prep_weights(const float* __restrict__ W_ih, const float* __restrict__ W_hh,
                  const float* __restrict__ b_ih, const float* __restrict__ b_hh,
                  const float* __restrict__ W1,   const float* __restrict__ W2,
                  const float* __restrict__ b2,   const float* __restrict__ W3,
                  const float* __restrict__ b3) {
    const int t = threadIdx.x;
    if (t < 16) {
        g_wbuf[OFF_WIHB + 4 * t + 0] = W_ih[2 * t];
        g_wbuf[OFF_WIHB + 4 * t + 1] = W_ih[2 * t + 1];
        g_wbuf[OFF_WIHB + 4 * t + 2] = b_ih[2 * t] + b_hh[2 * t];
        g_wbuf[OFF_WIHB + 4 * t + 3] = b_ih[2 * t + 1] + b_hh[2 * t + 1];
    }
    for (int i = t; i < 1024; i += 256)   // whh2 == raw row-major copy
        g_wbuf[OFF_WHH2 + i] = W_hh[i];
    for (int i = t; i < 512; i += 256) {  // w1c
        int col = 32 + (i >> 3), q = i & 7;
        g_wbuf[OFF_W1C + 2 * i + 0] = W1[(2 * q) * 96 + col];
        g_wbuf[OFF_W1C + 2 * i + 1] = W1[(2 * q + 1) * 96 + col];
    }
    if (t < 64) {                          // w2c
        int k = t >> 2, m = t & 3;
        g_wbuf[OFF_W2C + 2 * t + 0] = W2[(2 * m) * 16 + k];
        g_wbuf[OFF_W2C + 2 * t + 1] = W2[(2 * m + 1) * 16 + k];
    }
    if (t < 8) {
        g_wbuf[OFF_B2P + t] = b2[t];
        g_wbuf[OFF_W3P + t] = W3[t];
    }
    if (t == 0) g_wbuf[OFF_B3] = b3[0];
}

// ---------------- table build ----------------
__global__ __launch_bounds__(128)
void build_table(const float* __restrict__ W_ih, const float* __restrict__ W_hh,
                 const float* __restrict__ b_ih, const float* __restrict__ b_hh,
                 const float* __restrict__ W1,   const float* __restrict__ b1) {
    __shared__ float sWih[32], sBsum[32], sWhh[1024], sW1a[512], sB1[16];
    const int tid = threadIdx.x;
    for (int i = tid; i < 1024; i += 128) sWhh[i] = W_hh[i];
    for (int i = tid; i < 512;  i += 128) { int r = i >> 5, c = i & 31; sW1a[i] = W1[r * 96 + c]; }
    if (tid < 32) { sWih[tid] = W_ih[tid]; sBsum[tid] = b_ih[tid] + b_hh[tid]; }
    if (tid < 16) sB1[tid] = b1[tid];
    __syncthreads();

    const int idx = blockIdx.x * 128 + tid;
    if (idx >= TBL_N) return;
    const float x1 = TBL_LO + idx * TBL_STEP;

    float t[32], r[32];
#pragma unroll
    for (int j = 0; j < 32; j++) {
        t[j] = tanh_fast(fmaf(x1, sWih[j], sBsum[j]));
        r[j] = fmaxf(t[j], 0.0f);
    }
    for (int k = 0; k < 32; k++) {
        float f = sBsum[k];
#pragma unroll
        for (int j = 0; j < 32; j++) f = fmaf(sWhh[k * 32 + j], t[j], f);
        g_tbl[idx * 48 + k] = f;
    }
    for (int i = 0; i < 16; i++) {
        float g = sB1[i];
#pragma unroll
        for (int j = 0; j < 32; j++) g = fmaf(sW1a[i * 32 + j], r[j], g);
        g_tbl[idx * 48 + 32 + i] = g;
    }
}

// ---------------- main kernel: 2 elements / thread, weights in constant bank ----------------
__global__ __launch_bounds__(128, 3)
void rnn_main(const float* __restrict__ x, float* __restrict__ out, int n_half) {
    const int gid = blockIdx.x * 128 + threadIdx.x;
    if (gid >= n_half) return;

    // elements eA = 2*gid, eB = 2*gid+1; x flat: 6 floats per thread, 8B aligned
    const float2* xp = reinterpret_cast<const float2*>(x) + (size_t)gid * 3;
    float2 v0 = xp[0], v1 = xp[1], v2 = xp[2];
    const float x1A = v0.x, x2A = v0.y, x3A = v1.x;
    const float x1B = v1.y, x2B = v2.x, x3B = v2.y;

    // ---- stage-1 table lerp for both elements ----
    float ufA = fminf(fmaxf((x1A - TBL_LO) * TBL_INV, 0.0f), 8190.999f);
    float ufB = fminf(fmaxf((x1B - TBL_LO) * TBL_INV, 0.0f), 8190.999f);
    const int iA = (int)ufA, iB = (int)ufB;
    const float frA = ufA - (float)iA, frB = ufB - (float)iB;
    const u64 FRA = pk2(frA, frA), NFRA = pk2(-frA, -frA);
    const u64 FRB = pk2(frB, frB), NFRB = pk2(-frB, -frB);
    const float4* rlA = reinterpret_cast<const float4*>(g_tbl + iA * 48);
    const float4* rhA = reinterpret_cast<const float4*>(g_tbl + (iA + 1) * 48);
    const float4* rlB = reinterpret_cast<const float4*>(g_tbl + iB * 48);
    const float4* rhB = reinterpret_cast<const float4*>(g_tbl + (iB + 1) * 48);

    u64 accA[16], accB[16];  // pairs (k,k+1): step-2 preact, later h2
    u64 o1A[8],  o1B[8];     // pairs (i,i+1): fc1 accumulators
#pragma unroll
    for (int c = 0; c < 12; c++) {
        float4 loA = rlA[c], hiA = rhA[c];
        u64 rA0 = fma2(FRA, pk2(hiA.x, hiA.y), fma2(NFRA, pk2(loA.x, loA.y), pk2(loA.x, loA.y)));
        u64 rA1 = fma2(FRA, pk2(hiA.z, hiA.w), fma2(NFRA, pk2(loA.z, loA.w), pk2(loA.z, loA.w)));
        float4 loB = rlB[c], hiB = rhB[c];
        u64 rB0 = fma2(FRB, pk2(hiB.x, hiB.y), fma2(NFRB, pk2(loB.x, loB.y), pk2(loB.x, loB.y)));
        u64 rB1 = fma2(FRB, pk2(hiB.z, hiB.w), fma2(NFRB, pk2(loB.z, loB.w), pk2(loB.z, loB.w)));
        if (c < 8) { accA[2*c] = rA0; accA[2*c+1] = rA1; accB[2*c] = rB0; accB[2*c+1] = rB1; }
        else       { o1A[2*(c-8)] = rA0; o1A[2*(c-8)+1] = rA1; o1B[2*(c-8)] = rB0; o1B[2*(c-8)+1] = rB1; }
    }

    const u64 X2A = pk2(x2A, x2A), X2B = pk2(x2B, x2B);

    // ---- phase 2: h2 = tanh(acc + x2*wih) in place; o1 += relu(h2) x W1 cols 32..63 ----
#pragma unroll
    for (int p = 0; p < 16; p++) {
        const float4 wb = *reinterpret_cast<const float4*>(&cbuf[OFF_WIHB + 4 * p]);
        u64 W = pk2(wb.x, wb.y);
        float2 vA = up2(fma2(X2A, W, accA[p]));
        float2 vB = up2(fma2(X2B, W, accB[p]));
        float tA0 = tanh_fast(vA.x), tA1 = tanh_fast(vA.y);
        float tB0 = tanh_fast(vB.x), tB1 = tanh_fast(vB.y);
        accA[p] = pk2(tA0, tA1);
        accB[p] = pk2(tB0, tB1);
        u64 RA0 = pk2(fmaxf(tA0,0.f), fmaxf(tA0,0.f)), RA1 = pk2(fmaxf(tA1,0.f), fmaxf(tA1,0.f));
        u64 RB0 = pk2(fmaxf(tB0,0.f), fmaxf(tB0,0.f)), RB1 = pk2(fmaxf(tB1,0.f), fmaxf(tB1,0.f));
        const int c0 = 2 * p, c1 = 2 * p + 1;   // (col-32)
#pragma unroll
        for (int q = 0; q < 8; q += 2) {
            u64 wa0, wa1; ld2wc(OFF_W1C + 2 * (c0 * 8 + q), wa0, wa1);
            o1A[q]   = fma2(RA0, wa0, o1A[q]);   o1A[q+1] = fma2(RA0, wa1, o1A[q+1]);
            o1B[q]   = fma2(RB0, wa0, o1B[q]);   o1B[q+1] = fma2(RB0, wa1, o1B[q+1]);
            u64 wc0, wc1; ld2wc(OFF_W1C + 2 * (c1 * 8 + q), wc0, wc1);
            o1A[q]   = fma2(RA1, wc0, o1A[q]);   o1A[q+1] = fma2(RA1, wc1, o1A[q+1]);
            o1B[q]   = fma2(RB1, wc0, o1B[q]);   o1B[q+1] = fma2(RB1, wc1, o1B[q+1]);
        }
    }

    // ---- phase 3: h3_j = tanh(x3*wih_j + bsum_j + Whh[j]·h2); o1 += relu x W1 cols 64..95 ----
#pragma unroll 2
    for (int m = 0; m < 16; m++) {
        const int j0 = 2 * m, j1 = 2 * m + 1;
        u64 dA0 = 0ull, dA1 = 0ull, dB0 = 0ull, dB1 = 0ull;
#pragma unroll
        for (int p = 0; p < 16; p += 2) {
            u64 w0, w1; ld2wc(OFF_WHH2 + 2 * (j0 * 16 + p), w0, w1);
            dA0 = fma2(accA[p], w0, dA0); dA0 = fma2(accA[p+1], w1, dA0);
            dB0 = fma2(accB[p], w0, dB0); dB0 = fma2(accB[p+1], w1, dB0);
            u64 u0, u1; ld2wc(OFF_WHH2 + 2 * (j1 * 16 + p), u0, u1);
            dA1 = fma2(accA[p], u0, dA1); dA1 = fma2(accA[p+1], u1, dA1);
            dB1 = fma2(accB[p], u0, dB1); dB1 = fma2(accB[p+1], u1, dB1);
        }
        const float4 wb = *reinterpret_cast<const float4*>(&cbuf[OFF_WIHB + 4 * m]);
        float2 sA0 = up2(dA0), sA1 = up2(dA1), sB0 = up2(dB0), sB1v = up2(dB1);
        float tA0 = tanh_fast(fmaf(x3A, wb.x, wb.z) + (sA0.x + sA0.y));
        float tA1 = tanh_fast(fmaf(x3A, wb.y, wb.w) + (sA1.x + sA1.y));
        float tB0 = tanh_fast(fmaf(x3B, wb.x, wb.z) + (sB0.x + sB0.y));
        float tB1 = tanh_fast(fmaf(x3B, wb.y, wb.w) + (sB1v.x + sB1v.y));
        u64 RA0 = pk2(fmaxf(tA0,0.f), fmaxf(tA0,0.f)), RA1 = pk2(fmaxf(tA1,0.f), fmaxf(tA1,0.f));
        u64 RB0 = pk2(fmaxf(tB0,0.f), fmaxf(tB0,0.f)), RB1 = pk2(fmaxf(tB1,0.f), fmaxf(tB1,0.f));
        const int c0 = 32 + j0, c1 = 32 + j1;   // (col-32) for cols 64..95
#pragma unroll
        for (int q = 0; q < 8; q += 2) {
            u64 wa0, wa1; ld2wc(OFF_W1C + 2 * (c0 * 8 + q), wa0, wa1);
            o1A[q]   = fma2(RA0, wa0, o1A[q]);   o1A[q+1] = fma2(RA0, wa1, o1A[q+1]);
            o1B[q]   = fma2(RB0, wa0, o1B[q]);   o1B[q+1] = fma2(RB0, wa1, o1B[q+1]);
            u64 wc0, wc1; ld2wc(OFF_W1C + 2 * (c1 * 8 + q), wc0, wc1);
            o1A[q]   = fma2(RA1, wc0, o1A[q]);   o1A[q+1] = fma2(RA1, wc1, o1A[q+1]);
            o1B[q]   = fma2(RB1, wc0, o1B[q]);   o1B[q+1] = fma2(RB1, wc1, o1B[q+1]);
        }
    }

    // ---- fc2 ----
    u64 o2A[4], o2B[4];
#pragma unroll
    for (int m = 0; m < 4; m++) {
        const float2 b = *reinterpret_cast<const float2*>(&cbuf[OFF_B2P + 2 * m]);
        o2A[m] = pk2(b.x, b.y); o2B[m] = pk2(b.x, b.y);
    }
#pragma unroll
    for (int q = 0; q < 8; q++) {
        float2 vA = up2(o1A[q]), vB = up2(o1B[q]);
        u64 KaA = pk2(vA.x, vA.x), KbA = pk2(vA.y, vA.y);
        u64 KaB = pk2(vB.x, vB.x), KbB = pk2(vB.y, vB.y);
        const int k0 = 2 * q, k1 = 2 * q + 1;
        u64 w0, w1;
        ld2wc(OFF_W2C + 2 * (k0 * 4 + 0), w0, w1);
        o2A[0] = fma2(KaA, w0, o2A[0]); o2A[1] = fma2(KaA, w1, o2A[1]);
        o2B[0] = fma2(KaB, w0, o2B[0]); o2B[1] = fma2(KaB, w1, o2B[1]);
        ld2wc(OFF_W2C + 2 * (k0 * 4 + 2), w0, w1);
        o2A[2] = fma2(KaA, w0, o2A[2]); o2A[3] = fma2(KaA, w1, o2A[3]);
        o2B[2] = fma2(KaB, w0, o2B[2]); o2B[3] = fma2(KaB, w1, o2B[3]);
        ld2wc(OFF_W2C + 2 * (k1 * 4 + 0), w0, w1);
        o2A[0] = fma2(KbA, w0, o2A[0]); o2A[1] = fma2(KbA, w1, o2A[1]);
        o2B[0] = fma2(KbB, w0, o2B[0]); o2B[1] = fma2(KbB, w1, o2B[1]);
        ld2wc(OFF_W2C + 2 * (k1 * 4 + 2), w0, w1);
        o2A[2] = fma2(KbA, w0, o2A[2]); o2A[3] = fma2(KbA, w1, o2A[3]);
        o2B[2] = fma2(KbB, w0, o2B[2]); o2B[3] = fma2(KbB, w1, o2B[3]);
    }

    // ---- relu + fc3 ----
    u64 AA = 0ull, AB = 0ull;
#pragma unroll
    for (int m = 0; m < 4; m++) {
        const float2 w3 = *reinterpret_cast<const float2*>(&cbuf[OFF_W3P + 2 * m]);
        u64 w = pk2(w3.x, w3.y);
        AA = fma2(relu2(o2A[m]), w, AA);
        AB = fma2(relu2(o2B[m]), w, AB);
    }
    const float bias3 = cbuf[OFF_B3];
    float2 fa = up2(AA), fb = up2(AB);
    float2 res = make_float2(fa.x + fa.y + bias3, fb.x + fb.y + bias3);
    reinterpret_cast<float2*>(out)[gid] = res;
}

extern "C" void kernel_launch(void* const* d_in, const int* in_sizes, int n_in,
                              void* d_out, int out_size) {
    const float* x    = (const float*)d_in[0];
    const float* W_ih = (const float*)d_in[1];
    const float* W_hh = (const float*)d_in[2];
    const float* b_ih = (const float*)d_in[3];
    const float* b_hh = (const float*)d_in[4];
    const float* W1   = (const float*)d_in[5];
    const float* b1   = (const float*)d_in[6];
    const float* W2   = (const float*)d_in[7];
    const float* b2   = (const float*)d_in[8];
    const float* W3   = (const float*)d_in[9];
    const float* b3   = (const float*)d_in[10];
    float* out = (float*)d_out;

    const int B = in_sizes[0] / 3;   // x is [B, 3, 1]
    const int n_half = B / 2;        // B = 1048576 (even)

    prep_weights<<<1, 256>>>(W_ih, W_hh, b_ih, b_hh, W1, W2, b2, W3, b3);

    void* wbuf_dev = nullptr;
    cudaGetSymbolAddress(&wbuf_dev, g_wbuf);
    cudaMemcpyToSymbolAsync(cbuf, wbuf_dev, 2304 * sizeof(float), 0,
                            cudaMemcpyDeviceToDevice, 0);

    build_table<<<TBL_N / 128, 128>>>(W_ih, W_hh, b_ih, b_hh, W1, b1);
    rnn_main<<<(n_half + 127) / 128, 128>>>(x, out, n_half);
}

// round 7
// speedup vs baseline: 2.7957x; 1.0010x over previous
#include <cuda_runtime.h>
#include <cstdint>

// RNN_50036368998466: B=1048576, T=3, H=32, D_IN=1.
// Stage 1 tabulated (function of x1 only). Weight traffic split across ports:
//   Whh (256 LDS.128/warp) -> shared (L1 pipe),
//   W1c/W2/Wihb (~320 LDC.128/warp) -> constant bank (uniform port).
// R6 was co-bound on the half-rate constant port (LDC floor 8); the split makes
// the FFMA2 pipe (~65us) the binding resource. prep merged into build_table.

typedef unsigned long long u64;

#define TBL_N    8192
#define TBL_LO   (-10.0f)
#define TBL_STEP (20.0f / 8191.0f)
#define TBL_INV  (8191.0f / 20.0f)

__device__ __align__(16) float g_tbl[TBL_N * 48];
__device__ __align__(16) float g_wbuf[1536];
__constant__ __align__(16) float cbuf[1536];

// float offsets inside cbuf (16B aligned where float4-read)
#define OFF_WIHB 0      // float4[16]: (wih_2m, wih_2m+1, bsum_2m, bsum_2m+1)
#define OFF_W1C  64     // float2[512]: [(col-32)*8+q] = (W1[2q][col], W1[2q+1][col])
#define OFF_W2C  1088   // float2[64]:  [k*4+m] = (W2[2m][k], W2[2m+1][k])
#define OFF_B2P  1216   // float2[4]
#define OFF_W3P  1224   // float2[4]
#define OFF_B3   1232

__device__ __forceinline__ u64 pk2(float lo, float hi) {
    u64 r; asm("mov.b64 %0, {%1,%2};" : "=l"(r) : "f"(lo), "f"(hi)); return r;
}
__device__ __forceinline__ float2 up2(u64 v) {
    float2 r; asm("mov.b64 {%0,%1}, %2;" : "=f"(r.x), "=f"(r.y) : "l"(v)); return r;
}
__device__ __forceinline__ u64 fma2(u64 a, u64 b, u64 c) {
    u64 d; asm("fma.rn.f32x2 %0, %1, %2, %3;" : "=l"(d) : "l"(a), "l"(b), "l"(c)); return d;
}
// two packed weight operands from one 16B constant-bank read (compile-time index)
__device__ __forceinline__ void ld2wc(int fidx, u64& w0, u64& w1) {
    float4 v = *reinterpret_cast<const float4*>(&cbuf[fidx]);
    w0 = pk2(v.x, v.y);
    w1 = pk2(v.z, v.w);
}
// two packed weight operands from one LDS.128
__device__ __forceinline__ void ld2ws(const float* p, u64& w0, u64& w1) {
    float4 v = *reinterpret_cast<const float4*>(p);
    w0 = pk2(v.x, v.y);
    w1 = pk2(v.z, v.w);
}

// tanh(x) = 1 - 2/(exp(2x)+1) via ex2.approx + rcp.approx (abs err ~1e-7).
__device__ __forceinline__ float tanh_fast(float x) {
    float ex;
    asm("ex2.approx.f32 %0, %1;" : "=f"(ex) : "f"(x * 2.8853900817779268f)); // 2*log2(e)
    float r;
    asm("rcp.approx.f32 %0, %1;" : "=f"(r) : "f"(ex + 1.0f));
    return fmaf(-2.0f, r, 1.0f);
}
__device__ __forceinline__ u64 relu2(u64 a) {
    float2 v = up2(a);
    return pk2(fmaxf(v.x, 0.0f), fmaxf(v.y, 0.0f));
}

// ---------------- table build + weight pack (block 0 also packs) ----------------
__global__ __launch_bounds__(128)
void build_table(const float* __restrict__ W_ih, const float* __restrict__ W_hh,
                 const float* __restrict__ b_ih, const float* __restrict__ b_hh,
                 const float* __restrict__ W1,   const float* __restrict__ b1,
                 const float* __restrict__ W2,   const float* __restrict__ b2,
                 const float* __restrict__ W3,   const float* __restrict__ b3) {
    __shared__ float sWih[32], sBsum[32], sWhh[1024], sW1a[512], sB1[16];
    const int tid = threadIdx.x;
    for (int i = tid; i < 1024; i += 128) sWhh[i] = W_hh[i];
    for (int i = tid; i < 512;  i += 128) { int r = i >> 5, c = i & 31; sW1a[i] = W1[r * 96 + c]; }
    if (tid < 32) { sWih[tid] = W_ih[tid]; sBsum[tid] = b_ih[tid] + b_hh[tid]; }
    if (tid < 16) sB1[tid] = b1[tid];
    __syncthreads();

    if (blockIdx.x == 0) {  // weight pack for cbuf
        if (tid < 16) {
            g_wbuf[OFF_WIHB + 4 * tid + 0] = sWih[2 * tid];
            g_wbuf[OFF_WIHB + 4 * tid + 1] = sWih[2 * tid + 1];
            g_wbuf[OFF_WIHB + 4 * tid + 2] = sBsum[2 * tid];
            g_wbuf[OFF_WIHB + 4 * tid + 3] = sBsum[2 * tid + 1];
        }
        for (int i = tid; i < 512; i += 128) {
            int col = 32 + (i >> 3), q = i & 7;
            g_wbuf[OFF_W1C + 2 * i + 0] = W1[(2 * q) * 96 + col];
            g_wbuf[OFF_W1C + 2 * i + 1] = W1[(2 * q + 1) * 96 + col];
        }
        if (tid < 64) {
            int k = tid >> 2, m = tid & 3;
            g_wbuf[OFF_W2C + 2 * tid + 0] = W2[(2 * m) * 16 + k];
            g_wbuf[OFF_W2C + 2 * tid + 1] = W2[(2 * m + 1) * 16 + k];
        }
        if (tid < 8) {
            g_wbuf[OFF_B2P + tid] = b2[tid];
            g_wbuf[OFF_W3P + tid] = W3[tid];
        }
        if (tid == 0) g_wbuf[OFF_B3] = b3[0];
    }

    const int idx = blockIdx.x * 128 + tid;
    if (idx >= TBL_N) return;
    const float x1 = TBL_LO + idx * TBL_STEP;

    float t[32], r[32];
#pragma unroll
    for (int j = 0; j < 32; j++) {
        t[j] = tanh_fast(fmaf(x1, sWih[j], sBsum[j]));
        r[j] = fmaxf(t[j], 0.0f);
    }
    for (int k = 0; k < 32; k++) {
        float f = sBsum[k];
#pragma unroll
        for (int j = 0; j < 32; j++) f = fmaf(sWhh[k * 32 + j], t[j], f);
        g_tbl[idx * 48 + k] = f;
    }
    for (int i = 0; i < 16; i++) {
        float g = sB1[i];
#pragma unroll
        for (int j = 0; j < 32; j++) g = fmaf(sW1a[i * 32 + j], r[j], g);
        g_tbl[idx * 48 + 32 + i] = g;
    }
}

// ---------------- main kernel: 2 elements/thread; Whh in smem, rest in cbank ----------------
__global__ __launch_bounds__(128, 3)
void rnn_main(const float* __restrict__ x, const float* __restrict__ W_hh,
              float* __restrict__ out, int n_half) {
    __shared__ __align__(16) float sWhh[1024];   // row-major W_hh[j][k]
    const int tid = threadIdx.x;
    {
        const float4* src = reinterpret_cast<const float4*>(W_hh);
        float4* dst = reinterpret_cast<float4*>(sWhh);
#pragma unroll
        for (int i = tid; i < 256; i += 128) dst[i] = src[i];
    }
    __syncthreads();

    const int gid = blockIdx.x * 128 + tid;
    if (gid >= n_half) return;

    // elements eA = 2*gid, eB = 2*gid+1; x flat: 6 floats per thread, 8B aligned
    const float2* xp = reinterpret_cast<const float2*>(x) + (size_t)gid * 3;
    float2 v0 = xp[0], v1 = xp[1], v2 = xp[2];
    const float x1A = v0.x, x2A = v0.y, x3A = v1.x;
    const float x1B = v1.y, x2B = v2.x, x3B = v2.y;

    // ---- stage-1 table lerp for both elements ----
    float ufA = fminf(fmaxf((x1A - TBL_LO) * TBL_INV, 0.0f), 8190.999f);
    float ufB = fminf(fmaxf((x1B - TBL_LO) * TBL_INV, 0.0f), 8190.999f);
    const int iA = (int)ufA, iB = (int)ufB;
    const float frA = ufA - (float)iA, frB = ufB - (float)iB;
    const u64 FRA = pk2(frA, frA), NFRA = pk2(-frA, -frA);
    const u64 FRB = pk2(frB, frB), NFRB = pk2(-frB, -frB);
    const float4* rlA = reinterpret_cast<const float4*>(g_tbl + iA * 48);
    const float4* rhA = reinterpret_cast<const float4*>(g_tbl + (iA + 1) * 48);
    const float4* rlB = reinterpret_cast<const float4*>(g_tbl + iB * 48);
    const float4* rhB = reinterpret_cast<const float4*>(g_tbl + (iB + 1) * 48);

    u64 accA[16], accB[16];  // pairs (k,k+1): step-2 preact, later h2
    u64 o1A[8],  o1B[8];     // pairs (i,i+1): fc1 accumulators
#pragma unroll
    for (int c = 0; c < 12; c++) {
        float4 loA = rlA[c], hiA = rhA[c];
        u64 rA0 = fma2(FRA, pk2(hiA.x, hiA.y), fma2(NFRA, pk2(loA.x, loA.y), pk2(loA.x, loA.y)));
        u64 rA1 = fma2(FRA, pk2(hiA.z, hiA.w), fma2(NFRA, pk2(loA.z, loA.w), pk2(loA.z, loA.w)));
        float4 loB = rlB[c], hiB = rhB[c];
        u64 rB0 = fma2(FRB, pk2(hiB.x, hiB.y), fma2(NFRB, pk2(loB.x, loB.y), pk2(loB.x, loB.y)));
        u64 rB1 = fma2(FRB, pk2(hiB.z, hiB.w), fma2(NFRB, pk2(loB.z, loB.w), pk2(loB.z, loB.w)));
        if (c < 8) { accA[2*c] = rA0; accA[2*c+1] = rA1; accB[2*c] = rB0; accB[2*c+1] = rB1; }
        else       { o1A[2*(c-8)] = rA0; o1A[2*(c-8)+1] = rA1; o1B[2*(c-8)] = rB0; o1B[2*(c-8)+1] = rB1; }
    }

    const u64 X2A = pk2(x2A, x2A), X2B = pk2(x2B, x2B);

    // ---- phase 2: h2 = tanh(acc + x2*wih) in place; o1 += relu(h2) x W1 cols 32..63 ----
#pragma unroll
    for (int p = 0; p < 16; p++) {
        const float4 wb = *reinterpret_cast<const float4*>(&cbuf[OFF_WIHB + 4 * p]);
        u64 W = pk2(wb.x, wb.y);
        float2 vA = up2(fma2(X2A, W, accA[p]));
        float2 vB = up2(fma2(X2B, W, accB[p]));
        float tA0 = tanh_fast(vA.x), tA1 = tanh_fast(vA.y);
        float tB0 = tanh_fast(vB.x), tB1 = tanh_fast(vB.y);
        accA[p] = pk2(tA0, tA1);
        accB[p] = pk2(tB0, tB1);
        u64 RA0 = pk2(fmaxf(tA0,0.f), fmaxf(tA0,0.f)), RA1 = pk2(fmaxf(tA1,0.f), fmaxf(tA1,0.f));
        u64 RB0 = pk2(fmaxf(tB0,0.f), fmaxf(tB0,0.f)), RB1 = pk2(fmaxf(tB1,0.f), fmaxf(tB1,0.f));
        const int c0 = 2 * p, c1 = 2 * p + 1;   // (col-32)
#pragma unroll
        for (int q = 0; q < 8; q += 2) {
            u64 wa0, wa1; ld2wc(OFF_W1C + 2 * (c0 * 8 + q), wa0, wa1);
            o1A[q]   = fma2(RA0, wa0, o1A[q]);   o1A[q+1] = fma2(RA0, wa1, o1A[q+1]);
            o1B[q]   = fma2(RB0, wa0, o1B[q]);   o1B[q+1] = fma2(RB0, wa1, o1B[q+1]);
            u64 wc0, wc1; ld2wc(OFF_W1C + 2 * (c1 * 8 + q), wc0, wc1);
            o1A[q]   = fma2(RA1, wc0, o1A[q]);   o1A[q+1] = fma2(RA1, wc1, o1A[q+1]);
            o1B[q]   = fma2(RB1, wc0, o1B[q]);   o1B[q+1] = fma2(RB1, wc1, o1B[q+1]);
        }
    }

    // ---- phase 3: h3_j = tanh(x3*wih_j + bsum_j + Whh[j]·h2); o1 += relu x W1 cols 64..95 ----
#pragma unroll 2
    for (int m = 0; m < 16; m++) {
        const int j0 = 2 * m, j1 = 2 * m + 1;
        u64 dA0 = 0ull, dA1 = 0ull, dB0 = 0ull, dB1 = 0ull;
#pragma unroll
        for (int p = 0; p < 16; p += 2) {
            u64 w0, w1; ld2ws(&sWhh[j0 * 32 + 2 * p], w0, w1);
            dA0 = fma2(accA[p], w0, dA0); dA0 = fma2(accA[p+1], w1, dA0);
            dB0 = fma2(accB[p], w0, dB0); dB0 = fma2(accB[p+1], w1, dB0);
            u64 u0, u1; ld2ws(&sWhh[j1 * 32 + 2 * p], u0, u1);
            dA1 = fma2(accA[p], u0, dA1); dA1 = fma2(accA[p+1], u1, dA1);
            dB1 = fma2(accB[p], u0, dB1); dB1 = fma2(accB[p+1], u1, dB1);
        }
        const float4 wb = *reinterpret_cast<const float4*>(&cbuf[OFF_WIHB + 4 * m]);
        float2 sA0 = up2(dA0), sA1 = up2(dA1), sB0 = up2(dB0), sB1v = up2(dB1);
        float tA0 = tanh_fast(fmaf(x3A, wb.x, wb.z) + (sA0.x + sA0.y));
        float tA1 = tanh_fast(fmaf(x3A, wb.y, wb.w) + (sA1.x + sA1.y));
        float tB0 = tanh_fast(fmaf(x3B, wb.x, wb.z) + (sB0.x + sB0.y));
        float tB1 = tanh_fast(fmaf(x3B, wb.y, wb.w) + (sB1v.x + sB1v.y));
        u64 RA0 = pk2(fmaxf(tA0,0.f), fmaxf(tA0,0.f)), RA1 = pk2(fmaxf(tA1,0.f), fmaxf(tA1,0.f));
        u64 RB0 = pk2(fmaxf(tB0,0.f), fmaxf(tB0,0.f)), RB1 = pk2(fmaxf(tB1,0.f), fmaxf(tB1,0.f));
        const int c0 = 32 + j0, c1 = 32 + j1;   // (col-32) for cols 64..95
#pragma unroll
        for (int q = 0; q < 8; q += 2) {
            u64 wa0, wa1; ld2wc(OFF_W1C + 2 * (c0 * 8 + q), wa0, wa1);
            o1A[q]   = fma2(RA0, wa0, o1A[q]);   o1A[q+1] = fma2(RA0, wa1, o1A[q+1]);
            o1B[q]   = fma2(RB0, wa0, o1B[q]);   o1B[q+1] = fma2(RB0, wa1, o1B[q+1]);
            u64 wc0, wc1; ld2wc(OFF_W1C + 2 * (c1 * 8 + q), wc0, wc1);
            o1A[q]   = fma2(RA1, wc0, o1A[q]);   o1A[q+1] = fma2(RA1, wc1, o1A[q+1]);
            o1B[q]   = fma2(RB1, wc0, o1B[q]);   o1B[q+1] = fma2(RB1, wc1, o1B[q+1]);
        }
    }

    // ---- fc2 ----
    u64 o2A[4], o2B[4];
#pragma unroll
    for (int m = 0; m < 4; m++) {
        const float2 b = *reinterpret_cast<const float2*>(&cbuf[OFF_B2P + 2 * m]);
        o2A[m] = pk2(b.x, b.y); o2B[m] = pk2(b.x, b.y);
    }
#pragma unroll
    for (int q = 0; q < 8; q++) {
        float2 vA = up2(o1A[q]), vB = up2(o1B[q]);
        u64 KaA = pk2(vA.x, vA.x), KbA = pk2(vA.y, vA.y);
        u64 KaB = pk2(vB.x, vB.x), KbB = pk2(vB.y, vB.y);
        const int k0 = 2 * q, k1 = 2 * q + 1;
        u64 w0, w1;
        ld2wc(OFF_W2C + 2 * (k0 * 4 + 0), w0, w1);
        o2A[0] = fma2(KaA, w0, o2A[0]); o2A[1] = fma2(KaA, w1, o2A[1]);
        o2B[0] = fma2(KaB, w0, o2B[0]); o2B[1] = fma2(KaB, w1, o2B[1]);
        ld2wc(OFF_W2C + 2 * (k0 * 4 + 2), w0, w1);
        o2A[2] = fma2(KaA, w0, o2A[2]); o2A[3] = fma2(KaA, w1, o2A[3]);
        o2B[2] = fma2(KaB, w0, o2B[2]); o2B[3] = fma2(KaB, w1, o2B[3]);
        ld2wc(OFF_W2C + 2 * (k1 * 4 + 0), w0, w1);
        o2A[0] = fma2(KbA, w0, o2A[0]); o2A[1] = fma2(KbA, w1, o2A[1]);
        o2B[0] = fma2(KbB, w0, o2B[0]); o2B[1] = fma2(KbB, w1, o2B[1]);
        ld2wc(OFF_W2C + 2 * (k1 * 4 + 2), w0, w1);
        o2A[2] = fma2(KbA, w0, o2A[2]); o2A[3] = fma2(KbA, w1, o2A[3]);
        o2B[2] = fma2(KbB, w0, o2B[2]); o2B[3] = fma2(KbB, w1, o2B[3]);
    }

    // ---- relu + fc3 ----
    u64 AA = 0ull, AB = 0ull;
#pragma unroll
    for (int m = 0; m < 4; m++) {
        const float2 w3 = *reinterpret_cast<const float2*>(&cbuf[OFF_W3P + 2 * m]);
        u64 w = pk2(w3.x, w3.y);
        AA = fma2(relu2(o2A[m]), w, AA);
        AB = fma2(relu2(o2B[m]), w, AB);
    }
    const float bias3 = cbuf[OFF_B3];
    float2 fa = up2(AA), fb = up2(AB);
    float2 res = make_float2(fa.x + fa.y + bias3, fb.x + fb.y + bias3);
    reinterpret_cast<float2*>(out)[gid] = res;
}

extern "C" void kernel_launch(void* const* d_in, const int* in_sizes, int n_in,
                              void* d_out, int out_size) {
    const float* x    = (const float*)d_in[0];
    const float* W_ih = (const float*)d_in[1];
    const float* W_hh = (const float*)d_in[2];
    const float* b_ih = (const float*)d_in[3];
    const float* b_hh = (const float*)d_in[4];
    const float* W1   = (const float*)d_in[5];
    const float* b1   = (const float*)d_in[6];
    const float* W2   = (const float*)d_in[7];
    const float* b2   = (const float*)d_in[8];
    const float* W3   = (const float*)d_in[9];
    const float* b3   = (const float*)d_in[10];
    float* out = (float*)d_out;

    const int B = in_sizes[0] / 3;   // x is [B, 3, 1]
    const int n_half = B / 2;        // B = 1048576 (even)

    build_table<<<TBL_N / 128, 128>>>(W_ih, W_hh, b_ih, b_hh, W1, b1, W2, b2, W3, b3);

    void* wbuf_dev = nullptr;
    cudaGetSymbolAddress(&wbuf_dev, g_wbuf);
    cudaMemcpyToSymbolAsync(cbuf, wbuf_dev, 1536 * sizeof(float), 0,
                            cudaMemcpyDeviceToDevice, 0);

    rnn_main<<<(n_half + 127) / 128, 128>>>(x, W_hh, out, n_half);
}